// round 13
// baseline (speedup 1.0000x reference)
#include <cuda_runtime.h>
#include <cuda_fp16.h>
#include <cstdint>

// ---------------- problem constants ----------------
#define BB    4
#define NPTS  16384
#define KNN   16
#define CIN   64
#define CF    67
#define CP    72          // padded channels (cols 67..71 zero)
#define COUT  128
#define NTHR  256
#define NCH   17          // 1088/64 k-chunks
#define BLKB  17408       // bytes of AGG per 8-point block: 17ch * 1024B

// ---------------- global scratch ----------------
__device__ float g_featsCL[(size_t)BB * NPTS * CP];     // [B][N][72] point-major fp32
// LT fp16, HMMA A-frag order: [ch][w][ks][lane][16B]
__device__ __align__(128) uint32_t g_LT[NCH * 4096];
// AGG fp16, paired-ks GEMM-B-frag order: [block(8192)][ch(17)][ks2(2)][lane(32)][16B]
__device__ __align__(128) unsigned char g_AGG[(size_t)8192 * BLKB];

// ---------------- PTX helpers ----------------
__device__ __forceinline__ uint32_t smem_u32(const void* p) {
    uint32_t a;
    asm("{ .reg .u64 t; cvta.to.shared.u64 t, %1; cvt.u32.u64 %0, t; }" : "=r"(a) : "l"(p));
    return a;
}
#define MBAR_INIT(a, c)   asm volatile("mbarrier.init.shared.b64 [%0], %1;" :: "r"(a), "r"(c) : "memory")
#define MBAR_EXPECT(a, n) asm volatile("mbarrier.arrive.expect_tx.shared.b64 _, [%0], %1;" :: "r"(a), "r"(n) : "memory")
#define MBAR_ARRIVE(a)    asm volatile("mbarrier.arrive.shared.b64 _, [%0];" :: "r"(a) : "memory")
#define MBAR_INVAL(a)     asm volatile("mbarrier.inval.shared.b64 [%0];" :: "r"(a) : "memory")

__device__ __forceinline__ void mbar_wait(uint32_t mbar, uint32_t parity) {
    asm volatile(
        "{\n\t.reg .pred P1;\n\t"
        "WAIT_LOOP_%=:\n\t"
        "mbarrier.try_wait.parity.acquire.cta.shared::cta.b64 P1, [%0], %1, 0x989680;\n\t"
        "@P1 bra.uni WAIT_DONE_%=;\n\t"
        "bra.uni WAIT_LOOP_%=;\n\t"
        "WAIT_DONE_%=:\n\t}"
        :: "r"(mbar), "r"(parity) : "memory");
}
__device__ __forceinline__ void bulk_cp(uint32_t dst_smem, const void* src_gmem, uint32_t bytes, uint32_t mbar) {
    asm volatile(
        "cp.async.bulk.shared::cluster.global.mbarrier::complete_tx::bytes [%0], [%1], %2, [%3];"
        :: "r"(dst_smem), "l"((unsigned long long)src_gmem), "r"(bytes), "r"(mbar) : "memory");
}
__device__ __forceinline__ void bulk_st(void* dst_gmem, uint32_t src_smem, uint32_t bytes) {
    asm volatile(
        "cp.async.bulk.global.shared::cta.bulk_group [%0], [%1], %2;"
        :: "l"((unsigned long long)dst_gmem), "r"(src_smem), "r"(bytes) : "memory");
}
__device__ __forceinline__ void mma16816h(float* c, uint32_t a0, uint32_t a1, uint32_t a2, uint32_t a3,
                                          uint32_t b0, uint32_t b1) {
    asm volatile(
        "mma.sync.aligned.m16n8k16.row.col.f32.f16.f16.f32 "
        "{%0,%1,%2,%3}, {%4,%5,%6,%7}, {%8,%9}, {%0,%1,%2,%3};"
        : "+f"(c[0]), "+f"(c[1]), "+f"(c[2]), "+f"(c[3])
        : "r"(a0), "r"(a1), "r"(a2), "r"(a3), "r"(b0), "r"(b1));
}
__device__ __forceinline__ uint32_t packh2(float a, float b) {
    __half2 h = __floats2half2_rn(a, b);
    return *(uint32_t*)&h;
}

// ---------------------------------------------------------------------------
// Prep A: channel-major [B,C,N] -> point-major [B,N,72], float4 both sides
// ---------------------------------------------------------------------------
__global__ void prep_feats(const float* __restrict__ xyz, const float* __restrict__ feats) {
    __shared__ float tile[CP * 33];   // [c][32] stride-33
    const int b  = blockIdx.y;
    const int n0 = blockIdx.x * 32;
    for (int i = threadIdx.x; i < CP * 8; i += NTHR) {
        int c = i >> 3, q = i & 7;
        float4 v = make_float4(0.f, 0.f, 0.f, 0.f);
        if (c < 3)       v = *(const float4*)&xyz[((size_t)b * 3 + c) * NPTS + n0 + q * 4];
        else if (c < CF) v = *(const float4*)&feats[((size_t)b * CIN + (c - 3)) * NPTS + n0 + q * 4];
        tile[c * 33 + q * 4 + 0] = v.x;
        tile[c * 33 + q * 4 + 1] = v.y;
        tile[c * 33 + q * 4 + 2] = v.z;
        tile[c * 33 + q * 4 + 3] = v.w;
    }
    __syncthreads();
    for (int i = threadIdx.x; i < 32 * (CP / 4); i += NTHR) {
        int p = i / (CP / 4), q = i - p * (CP / 4);
        float4 v = make_float4(tile[(q*4+0)*33 + p], tile[(q*4+1)*33 + p],
                               tile[(q*4+2)*33 + p], tile[(q*4+3)*33 + p]);
        *(float4*)&g_featsCL[((size_t)b * NPTS + n0 + p) * CP + q * 4] = v;
    }
}

// ---------------------------------------------------------------------------
// Prep B: lin_w -> fp16 plane in A-frag order [ch][w][ks][lane][r]
// ---------------------------------------------------------------------------
__global__ void prep_lt(const float* __restrict__ lin_w) {
    int idx = blockIdx.x * NTHR + threadIdx.x;
    if (idx >= NCH * 4096) return;
    int r    = idx & 3;
    int lane = (idx >> 2) & 31;
    int ks   = (idx >> 7) & 3;
    int w    = (idx >> 9) & 7;
    int ch   = idx >> 12;
    int row = (lane >> 2) + ((r & 1) ? 8 : 0);
    int fk  = (lane & 3) * 2 + ((r >= 2) ? 8 : 0);
    int o   = w * 16 + row;
    float v[2];
#pragma unroll
    for (int e = 0; e < 2; e++) {
        int kg = ch * 64 + ks * 16 + fk + e;
        int wr = kg / 68, c = kg - wr * 68;
        v[e] = (c < CF) ? lin_w[(size_t)o * (16 * CF) + wr * CF + c] : 0.f;
    }
    g_LT[idx] = packh2(v[0], v[1]);
}

// ---------------------------------------------------------------------------
// pc_agg: gather + weight-net + inner MMA -> AGG fp16 (paired-ks B-frag order)
// 16 points per CTA, 8 warps x 2 points, 3 CTAs/SM
// ---------------------------------------------------------------------------
#define SMA_AGG 0            // 34816 = 2 blocks x 17408
#define SMA_WT  34816        // 8704
#define SMA_IDX 43520        // 1024 (8 warps x 32 ints)
#define SMA_PAR 44544        // 704
#define SMA_BYTES 45248

__device__ __forceinline__ void store_agg_pair(char* aggbase, int p, int w, int c, float v0, float v1) {
    if (c >= 68) return;                     // c even; pair (c, c+1)
    int kg = w * 68 + c;
    int ch = kg >> 6, kl = kg & 63;
    int ks = kl >> 4, kl2 = kl & 15;
    uint32_t off = (uint32_t)((p >> 3) * BLKB + ch * 1024 + (ks >> 1) * 512
                   + ((p & 7) * 4 + ((kl2 >> 1) & 3)) * 16 + (ks & 1) * 8 + (kl2 >> 3) * 4);
    *(__half2*)(aggbase + off) = __floats2half2_rn(v0, v1);
}

__global__ __launch_bounds__(NTHR, 3)
void pc_agg(const int*   __restrict__ knn,
            const float* __restrict__ w1, const float* __restrict__ b1,
            const float* __restrict__ w2, const float* __restrict__ b2)
{
    extern __shared__ __align__(128) char smem[];
    const uint32_t sb = smem_u32(smem);
    const int tid  = threadIdx.x;
    const int warp = tid >> 5;
    const int lane = tid & 31;
    const int b    = blockIdx.x >> 10;             // 1024 CTAs per batch
    const int pb   = (blockIdx.x & 1023) * 16;
    const size_t fb = (size_t)b * NPTS;

    float* sPar = (float*)(smem + SMA_PAR);
    if (tid < 176) {
        float v;
        if      (tid < 24)  v = w1[tid];
        else if (tid < 32)  v = b1[tid - 24];
        else if (tid < 160) v = w2[tid - 32];
        else                v = b2[tid - 160];
        sPar[tid] = v;
    }
    __syncthreads();

    float* myWt  = (float*)(smem + SMA_WT) + warp * 272;   // [k][17]
    int*   myIdx = (int*)(smem + SMA_IDX) + warp * 32;
    const float* W1 = sPar;       const float* B1 = sPar + 24;
    const float* W2 = sPar + 32;  const float* B2 = sPar + 160;
    const int kp   = (lane & 3) * 2;
    const int wrow = lane >> 2;
    const int cl   = lane >> 2;

    // preload this warp's 2 points x 16 knn indices (1 LDG/lane)
    myIdx[lane] = knn[(fb + pb + warp * 2 + (lane >> 4)) * KNN + (lane & 15)];
    __syncwarp();

    for (int r = 0; r < 2; r++) {
        const int p = warp * 2 + r;
        const int* idx = myIdx + r * 16;

        // ---- issue ALL gather loads first (36 B-frag + weight-net inputs) ----
        const float* r0p = g_featsCL + (fb + idx[kp])     * CP;
        const float* r1p = g_featsCL + (fb + idx[kp + 1]) * CP;
        const float* r2p = g_featsCL + (fb + idx[kp + 8]) * CP;
        const float* r3p = g_featsCL + (fb + idx[kp + 9]) * CP;
        float f0[9], f1[9], f2[9], f3[9];
#pragma unroll
        for (int cb = 0; cb < 9; cb++) {
            int c = cb * 8 + cl;
            f0[cb] = r0p[c]; f1[cb] = r1p[c]; f2[cb] = r2p[c]; f3[cb] = r3p[c];
        }
        const float* crow = g_featsCL + (fb + pb + p) * CP;
        const float cx = crow[0], cy = crow[1], cz = crow[2];
        const int kw = lane >> 1, half = lane & 1;
        const float* nrow = g_featsCL + (fb + idx[kw]) * CP;
        const float dx = nrow[0] - cx, dy = nrow[1] - cy, dz = nrow[2] - cz;

        // ---- weight-net (overlaps the in-flight gather loads) ----
        {
            float h[8];
#pragma unroll
            for (int j = 0; j < 8; j++) {
                float v = W1[j*3]*dx + W1[j*3+1]*dy + W1[j*3+2]*dz + B1[j];
                h[j] = fmaxf(v, 0.1f * v);
            }
#pragma unroll
            for (int wv = 0; wv < 8; wv++) {
                int w = half * 8 + wv;
                float s = B2[w];
#pragma unroll
                for (int j = 0; j < 8; j++) s += W2[w*8 + j] * h[j];
                myWt[kw * 17 + w] = fmaxf(s, 0.1f * s);
            }
        }
        __syncwarp();

        // A fragment: A[w][k] = myWt[k*17 + w]
        uint32_t a0 = packh2(myWt[kp*17 + wrow],         myWt[(kp+1)*17 + wrow]);
        uint32_t a1 = packh2(myWt[kp*17 + wrow + 8],     myWt[(kp+1)*17 + wrow + 8]);
        uint32_t a2 = packh2(myWt[(kp+8)*17 + wrow],     myWt[(kp+9)*17 + wrow]);
        uint32_t a3 = packh2(myWt[(kp+8)*17 + wrow + 8], myWt[(kp+9)*17 + wrow + 8]);

#pragma unroll
        for (int cb = 0; cb < 9; cb++) {
            uint32_t bb0 = packh2(f0[cb], f1[cb]);
            uint32_t bb1 = packh2(f2[cb], f3[cb]);
            float c4[4] = {0.f, 0.f, 0.f, 0.f};
            mma16816h(c4, a0, a1, a2, a3, bb0, bb1);
            int cc = cb * 8 + (lane & 3) * 2;
            store_agg_pair(smem, p, wrow,     cc, c4[0], c4[1]);
            store_agg_pair(smem, p, wrow + 8, cc, c4[2], c4[3]);
        }
        __syncwarp();
    }
    __syncthreads();
    asm volatile("fence.proxy.async.shared::cta;" ::: "memory");
    if (tid == 0) {
        bulk_st(g_AGG + (size_t)blockIdx.x * 2 * BLKB, sb + SMA_AGG, 2 * BLKB);
        asm volatile("cp.async.bulk.commit_group;" ::: "memory");
        asm volatile("cp.async.bulk.wait_group 0;" ::: "memory");
    }
}

// ---------------------------------------------------------------------------
// pc_gemm: out[128 x 128pts] per CTA; 2-stage x 1-chunk pipeline, 3 CTAs/SM
// stage = 16KB LT + 16KB AGG (16 blocks)
// ---------------------------------------------------------------------------
#define SUB_B    32768                   // 16K LT + 16K AGG
#define SMG_BAR  (2 * SUB_B)             // full[0..1] then empty[0..1]
#define SMG_BYTES (SMG_BAR + 128)

__global__ __launch_bounds__(NTHR, 3)
void pc_gemm(const float* __restrict__ lin_b, float* __restrict__ out)
{
    extern __shared__ __align__(128) char smem[];
    const uint32_t sb = smem_u32(smem);
    const int tid  = threadIdx.x;
    const int warp = tid >> 5;
    const int lane = tid & 31;
    const int b    = blockIdx.x >> 7;              // 128 CTAs per batch
    const int pb   = (blockIdx.x & 127) * 128;
    const int gb0  = blockIdx.x * 16;              // first 8-pt AGG block

    if (tid == 0) {
#pragma unroll
        for (int s = 0; s < 2; s++) {
            MBAR_INIT(sb + SMG_BAR + s * 8, 1);        // full
            MBAR_INIT(sb + SMG_BAR + 16 + s * 8, 8);   // empty (8 warp arrivals)
        }
    }
    __syncthreads();
    // prefetch chunks 0,1
    if (tid == 0) {
#pragma unroll
        for (int s = 0; s < 2; s++) {
            const uint32_t bar = sb + SMG_BAR + s * 8;
            const uint32_t stg = sb + s * SUB_B;
            MBAR_EXPECT(bar, SUB_B);
            bulk_cp(stg, g_LT + s * 4096, 16384, bar);
#pragma unroll
            for (int nb = 0; nb < 16; nb++)
                bulk_cp(stg + 16384 + nb * 1024,
                        g_AGG + (size_t)(gb0 + nb) * BLKB + s * 1024, 1024, bar);
        }
    }

    float acc[16][4];
#pragma unroll
    for (int nb = 0; nb < 16; nb++) { acc[nb][0] = acc[nb][1] = acc[nb][2] = acc[nb][3] = 0.f; }

    for (int ch = 0; ch < NCH; ch++) {
        const int s = ch & 1;
        const int phase = (ch >> 1) & 1;
        mbar_wait(sb + SMG_BAR + s * 8, phase);
        const uint32_t A  = sb + s * SUB_B + warp * 2048 + lane * 16;
        const uint32_t Bb = sb + s * SUB_B + 16384 + lane * 16;
#pragma unroll
        for (int kp2 = 0; kp2 < 2; kp2++) {
            uint32_t ae0, ae1, ae2, ae3, ao0, ao1, ao2, ao3;
            asm volatile("ld.shared.v4.u32 {%0,%1,%2,%3}, [%4];"
                         : "=r"(ae0), "=r"(ae1), "=r"(ae2), "=r"(ae3)
                         : "r"(A + (2 * kp2) * 512));
            asm volatile("ld.shared.v4.u32 {%0,%1,%2,%3}, [%4];"
                         : "=r"(ao0), "=r"(ao1), "=r"(ao2), "=r"(ao3)
                         : "r"(A + (2 * kp2 + 1) * 512));
#pragma unroll
            for (int nb = 0; nb < 16; nb++) {
                uint32_t be0, be1, bo0, bo1;
                asm volatile("ld.shared.v4.u32 {%0,%1,%2,%3}, [%4];"
                             : "=r"(be0), "=r"(be1), "=r"(bo0), "=r"(bo1)
                             : "r"(Bb + nb * 1024 + kp2 * 512));
                mma16816h(acc[nb], ae0, ae1, ae2, ae3, be0, be1);
                mma16816h(acc[nb], ao0, ao1, ao2, ao3, bo0, bo1);
            }
        }
        if (lane == 0) MBAR_ARRIVE(sb + SMG_BAR + 16 + s * 8);
        if (tid == 0 && ch + 2 < NCH) {
            // recycle stage s once all 8 warps consumed chunk ch
            mbar_wait(sb + SMG_BAR + 16 + s * 8, phase);
            const uint32_t bar = sb + SMG_BAR + s * 8;
            const uint32_t stg = sb + s * SUB_B;
            MBAR_EXPECT(bar, SUB_B);
            bulk_cp(stg, g_LT + (ch + 2) * 4096, 16384, bar);
#pragma unroll
            for (int nb = 0; nb < 16; nb++)
                bulk_cp(stg + 16384 + nb * 1024,
                        g_AGG + (size_t)(gb0 + nb) * BLKB + (ch + 2) * 1024, 1024, bar);
        }
    }

    // epilogue: bias + leaky + float2 stores
    {
        const int wrow = lane >> 2, pc2 = (lane & 3) * 2;
#pragma unroll
        for (int h = 0; h < 2; h++) {
            const int o = warp * 16 + wrow + h * 8;
            const float bias = __ldg(&lin_b[o]);
            float* orow = out + ((size_t)b * COUT + o) * NPTS + pb;
#pragma unroll
            for (int nb = 0; nb < 16; nb++) {
                float x0 = acc[nb][h*2 + 0] + bias;
                float x1 = acc[nb][h*2 + 1] + bias;
                float2 v = make_float2(fmaxf(x0, 0.1f * x0), fmaxf(x1, 0.1f * x1));
                *(float2*)(orow + nb * 8 + pc2) = v;
            }
        }
    }
    __syncthreads();
    if (tid == 0) {
#pragma unroll
        for (int s = 0; s < 2; s++) {
            MBAR_INVAL(sb + SMG_BAR + s * 8);
            MBAR_INVAL(sb + SMG_BAR + 16 + s * 8);
        }
    }
}

// ---------------------------------------------------------------------------
extern "C" void kernel_launch(void* const* d_in, const int* in_sizes, int n_in,
                              void* d_out, int out_size) {
    const float* xyz   = (const float*)d_in[0];
    const float* feats = (const float*)d_in[1];
    const int*   knn   = (const int*)d_in[2];
    const float* w1    = (const float*)d_in[3];
    const float* b1    = (const float*)d_in[4];
    const float* w2    = (const float*)d_in[5];
    const float* b2    = (const float*)d_in[6];
    const float* lin_w = (const float*)d_in[7];
    const float* lin_b = (const float*)d_in[8];
    float* out = (float*)d_out;

    cudaFuncSetAttribute(pc_agg,  cudaFuncAttributeMaxDynamicSharedMemorySize, SMA_BYTES);
    cudaFuncSetAttribute(pc_gemm, cudaFuncAttributeMaxDynamicSharedMemorySize, SMG_BYTES);

    prep_feats<<<dim3(NPTS / 32, BB), NTHR>>>(xyz, feats);
    prep_lt<<<(NCH * 4096 + NTHR - 1) / NTHR, NTHR>>>(lin_w);
    pc_agg<<<BB * NPTS / 16, NTHR, SMA_BYTES>>>(knn, w1, b1, w2, b2);
    pc_gemm<<<BB * NPTS / 128, NTHR, SMG_BYTES>>>(lin_b, out);
}